// round 3
// baseline (speedup 1.0000x reference)
#include <cuda_runtime.h>

// ---------------------------------------------------------------------------
// QuantumSentenceTransformer fused kernel, round 3.
//
// One thread per row. Warp-private cp.async staging: each warp streams its
// own 32 rows through a private 3-stage x 2KB smem ring, synchronized ONLY
// with per-warp wait_group + __syncwarp (no __syncthreads anywhere).
// XOR-swizzled layout is bank-conflict-free for both the cp.async stores and
// the per-row LDS.128 reads. W_pre in __constant__ (LDCU uniform port),
// matvec in packed fma.rn.f32x2, 16-dim statevector in registers.
// ---------------------------------------------------------------------------

#define DCOLS    512
#define BROWS    128            // rows per block == threads per block
#define CH       16             // columns per pipeline stage
#define NCHUNK   (DCOLS / CH)   // 32
#define STAGES   3
#define WSTAGE_F 512            // floats per warp-stage (32 rows x 16 cols) = 2KB

__constant__ float cW[DCOLS * 4];   // W_pre row-major [d][q], 8KB

// ---- f32x2 packed math -----------------------------------------------------
__device__ __forceinline__ unsigned long long ffma2(
    unsigned long long a, unsigned long long b, unsigned long long c) {
    unsigned long long d;
    asm("fma.rn.f32x2 %0, %1, %2, %3;" : "=l"(d) : "l"(a), "l"(b), "l"(c));
    return d;
}
__device__ __forceinline__ unsigned long long pack2(float x) {
    unsigned long long p;
    unsigned int u = __float_as_uint(x);
    asm("mov.b64 %0, {%1, %1};" : "=l"(p) : "r"(u));
    return p;
}
__device__ __forceinline__ void unpack2(unsigned long long p, float& lo, float& hi) {
    asm("mov.b64 {%0, %1}, %2;" : "=f"(lo), "=f"(hi) : "l"(p));
}

// ---- cp.async --------------------------------------------------------------
__device__ __forceinline__ void cp_async16(unsigned int dst, const void* src) {
    asm volatile("cp.async.cg.shared.global [%0], [%1], 16;"
                 :: "r"(dst), "l"(src));
}
__device__ __forceinline__ void cp_commit() {
    asm volatile("cp.async.commit_group;");
}
__device__ __forceinline__ void cp_wait1() {
    asm volatile("cp.async.wait_group 1;");
}
__device__ __forceinline__ void cp_wait0() {
    asm volatile("cp.async.wait_group 0;");
}

__device__ __forceinline__ float fast_tanh(float x) {
    float t = __expf(2.0f * x);
    return 1.0f - __fdividef(2.0f, t + 1.0f);
}

// RY on index-bit b. Fully unrolled; constant b.
__device__ __forceinline__ void ry_gate(float* s, float c, float sn, int b) {
#pragma unroll
    for (int i = 0; i < 16; ++i) {
        if (!((i >> b) & 1)) {
            int j = i | (1 << b);
            float a0 = s[i], a1 = s[j];
            s[i] = fmaf(c, a0, -sn * a1);
            s[j] = fmaf(sn, a0,  c * a1);
        }
    }
}
// CNOT: pure register rename.
__device__ __forceinline__ void cnot_gate(float* s, int cb, int tb) {
#pragma unroll
    for (int i = 0; i < 16; ++i) {
        if (((i >> cb) & 1) && !((i >> tb) & 1)) {
            int j = i | (1 << tb);
            float t = s[i]; s[i] = s[j]; s[j] = t;
        }
    }
}

__global__ __launch_bounds__(BROWS, 8)
void qst_kernel(const float* __restrict__ X,
                const float* __restrict__ bpre,
                const float* __restrict__ qp,
                const float* __restrict__ wpost,
                const float* __restrict__ bpost,
                float* __restrict__ out)
{
    __shared__ __align__(16) float sX[4 * STAGES * WSTAGE_F];   // 24KB

    const int tid  = threadIdx.x;
    const int lane = tid & 31;
    const int w    = tid >> 5;
    const long rowBase = (long)blockIdx.x * BROWS;

    // ---- warp-private loader mapping: 4 cp.async per lane per stage ------
    // idx = lane + 32*j ; r = idx>>2 (0..31) ; c4 = idx&3
    // gmem : row (rowBase + w*32 + r), cols [ch*16 + c4*4 .. +3]
    // smem : slot r*4 + (c4 ^ ((r>>1)&3))  within the warp-stage (128 slots)
    const char* gsrc[4];
    unsigned int sdst[4];
    const unsigned int wbase =
        (unsigned int)__cvta_generic_to_shared(sX) + (unsigned int)w * (STAGES * WSTAGE_F * 4);
#pragma unroll
    for (int j = 0; j < 4; ++j) {
        int idx = lane + 32 * j;
        int r   = idx >> 2;
        int c4  = idx & 3;
        gsrc[j] = (const char*)(X + (rowBase + w * 32 + r) * DCOLS + c4 * 4);
        int slot = r * 4 + (c4 ^ ((r >> 1) & 3));
        sdst[j] = wbase + (unsigned int)slot * 16u;
    }

    // ---- compute-side read addressing ------------------------------------
    const float4* const sx4 = reinterpret_cast<const float4*>(sX);
    const int myBase = w * (STAGES * (WSTAGE_F / 4)) + lane * 4;   // float4 units
    const int sw = (lane >> 1) & 3;
    const ulonglong2* const cW2 = reinterpret_cast<const ulonglong2*>(cW);

    unsigned long long acc01 = 0ull, acc23 = 0ull;

    // ---- prologue: stages 0 and 1 ----------------------------------------
#pragma unroll
    for (int j = 0; j < 4; ++j) cp_async16(sdst[j], gsrc[j]);
    cp_commit();
#pragma unroll
    for (int j = 0; j < 4; ++j) cp_async16(sdst[j] + WSTAGE_F * 4, gsrc[j] + CH * 4);
    cp_commit();

    // ---- warp-private pipelined matvec -----------------------------------
#pragma unroll 1
    for (int ch = 0; ch < NCHUNK; ++ch) {
        if (ch == NCHUNK - 1) cp_wait0(); else cp_wait1();   // stage ch landed
        __syncwarp();                                        // publish within warp

        const float4* srow = sx4 + myBase + (ch % STAGES) * (WSTAGE_F / 4);
#pragma unroll
        for (int c4 = 0; c4 < 4; ++c4) {
            float4 x = srow[c4 ^ sw];
            float xs[4] = {x.x, x.y, x.z, x.w};
            int d = ch * CH + c4 * 4;
#pragma unroll
            for (int k = 0; k < 4; ++k) {
                ulonglong2 wv = cW2[d + k];
                unsigned long long xp = pack2(xs[k]);
                acc01 = ffma2(xp, wv.x, acc01);
                acc23 = ffma2(xp, wv.y, acc23);
            }
        }

        // Refill slot (ch+2)%3 — last read at chunk ch-1; top-of-iteration
        // __syncwarp guarantees all lanes finished that read.
        if (ch + 2 < NCHUNK) {
            unsigned int so = (unsigned int)(((ch + 2) % STAGES) * WSTAGE_F * 4);
            const long go = (long)(ch + 2) * (CH * 4);
#pragma unroll
            for (int j = 0; j < 4; ++j) cp_async16(sdst[j] + so, gsrc[j] + go);
            cp_commit();
        }
    }

    float acc0, acc1, acc2, acc3;
    unpack2(acc01, acc0, acc1);
    unpack2(acc23, acc2, acc3);

    // ---- encoder angles ---------------------------------------------------
    const float PI4 = 0.7853981633974483f;
    float h0 = fast_tanh(acc0 + __ldg(bpre + 0)) * PI4;
    float h1 = fast_tanh(acc1 + __ldg(bpre + 1)) * PI4;
    float h2 = fast_tanh(acc2 + __ldg(bpre + 2)) * PI4;
    float h3 = fast_tanh(acc3 + __ldg(bpre + 3)) * PI4;

    // ---- quantum circuit (16-dim statevector in registers) ----------------
    float s[16];
#pragma unroll
    for (int i = 0; i < 16; ++i) s[i] = 0.25f;

    ry_gate(s, __cosf(h0), __sinf(h0), 3);
    ry_gate(s, __cosf(h1), __sinf(h1), 2);
    ry_gate(s, __cosf(h2), __sinf(h2), 1);
    ry_gate(s, __cosf(h3), __sinf(h3), 0);

#pragma unroll
    for (int k = 0; k < 6; ++k) {
        cnot_gate(s, 3, 2);
        cnot_gate(s, 1, 0);
        cnot_gate(s, 2, 1);
        { float h = __ldg(qp + 4*k + 0) * 0.5f; ry_gate(s, __cosf(h), __sinf(h), 3); }
        { float h = __ldg(qp + 4*k + 1) * 0.5f; ry_gate(s, __cosf(h), __sinf(h), 2); }
        { float h = __ldg(qp + 4*k + 2) * 0.5f; ry_gate(s, __cosf(h), __sinf(h), 1); }
        { float h = __ldg(qp + 4*k + 3) * 0.5f; ry_gate(s, __cosf(h), __sinf(h), 0); }
    }

    // ---- <Z_w> expectation values -----------------------------------------
    float e0 = 0.f, e1 = 0.f, e2 = 0.f, e3 = 0.f;
#pragma unroll
    for (int i = 0; i < 16; ++i) {
        float p = s[i] * s[i];
        e0 += ((i >> 3) & 1) ? -p : p;
        e1 += ((i >> 2) & 1) ? -p : p;
        e2 += ((i >> 1) & 1) ? -p : p;
        e3 += ( i       & 1) ? -p : p;
    }

    // ---- post head --------------------------------------------------------
    float o0 = __ldg(bpost + 0);
    float o1 = __ldg(bpost + 1);
    o0 = fmaf(e0, __ldg(wpost + 0), o0); o1 = fmaf(e0, __ldg(wpost + 1), o1);
    o0 = fmaf(e1, __ldg(wpost + 2), o0); o1 = fmaf(e1, __ldg(wpost + 3), o1);
    o0 = fmaf(e2, __ldg(wpost + 4), o0); o1 = fmaf(e2, __ldg(wpost + 5), o1);
    o0 = fmaf(e3, __ldg(wpost + 6), o0); o1 = fmaf(e3, __ldg(wpost + 7), o1);

    reinterpret_cast<float2*>(out)[rowBase + tid] = make_float2(o0, o1);
}

extern "C" void kernel_launch(void* const* d_in, const int* in_sizes, int n_in,
                              void* d_out, int out_size)
{
    const float* X     = (const float*)d_in[0];
    const float* bpre  = (const float*)d_in[2];
    const float* qp    = (const float*)d_in[3];
    const float* wpost = (const float*)d_in[4];
    const float* bpost = (const float*)d_in[5];

    cudaMemcpyToSymbolAsync(cW, d_in[1], DCOLS * 4 * sizeof(float), 0,
                            cudaMemcpyDeviceToDevice, 0);

    int B = in_sizes[0] / DCOLS;          // 131072
    qst_kernel<<<B / BROWS, BROWS, 0, 0>>>(X, bpre, qp, wpost, bpost,
                                           (float*)d_out);
}